// round 12
// baseline (speedup 1.0000x reference)
#include <cuda_runtime.h>
#include <cuda_bf16.h>
#include <math.h>

#define KG   256
#define DG   12
#define CG   9
#define HG   32
#define NIN  15
#define NEPS 1e-8f
#define LOG2E 1.4426950408889634f

typedef unsigned long long ull;

struct alignas(16) GPair {                 // params for gaussians (2p, 2p+1)
    ulonglong2 c00_01;   // coeffs pre-scaled by -0.5*log2e (offdiag x2)
    ulonglong2 c02_11;
    ulonglong2 c12_22;
    ulonglong2 nmux_y;   // (-mux pair, -muy pair)
    ulonglong2 nmuz_r2;  // (-muz pair, rad^2 pair)
};

struct CParams {
    GPair       gp[KG/2];     // 10 KB
    ulonglong2  F[KG * 3];    // 12 KB (F rows as f32x2 packs)
    float4      W1[HG * 4];   // 2 KB  (W1^T, slot15 = b1[j])
    float4      W2[HG * 3];   // 1.5 KB
    float4      b2v[3];
};

__device__   CParams d_prep;
__constant__ CParams c_p;

__device__ __forceinline__ ull add2(ull a, ull b) {
    ull r; asm("add.rn.f32x2 %0, %1, %2;" : "=l"(r) : "l"(a), "l"(b)); return r;
}
__device__ __forceinline__ ull mul2(ull a, ull b) {
    ull r; asm("mul.rn.f32x2 %0, %1, %2;" : "=l"(r) : "l"(a), "l"(b)); return r;
}
__device__ __forceinline__ void ffma2(ull& acc, ull a, ull b) {
    asm("fma.rn.f32x2 %0, %1, %2, %0;" : "+l"(acc) : "l"(a), "l"(b));
}
__device__ __forceinline__ ull bcast2(float x) {
    ull r; asm("mov.b64 %0, {%1, %1};" : "=l"(r) : "f"(x)); return r;
}
__device__ __forceinline__ void unpk(float& lo, float& hi, ull p) {
    asm("mov.b64 {%0, %1}, %2;" : "=f"(lo), "=f"(hi) : "l"(p));
}

template<bool ADD_LI>
__device__ __forceinline__ void eval_pair(
    const GPair& gp, ull ppx, ull ppy, ull ppz, ull lip,
    float& w0, float& w1)
{
    ull dxp = add2(ppx, gp.nmux_y.x);
    ull dyp = add2(ppy, gp.nmux_y.y);
    ull dzp = add2(ppz, gp.nmuz_r2.x);
    ull d2p = mul2(dzp, dzp); ffma2(d2p, dyp, dyp); ffma2(d2p, dxp, dxp);
    ull Ap  = mul2(gp.c02_11.x, dzp); ffma2(Ap, gp.c00_01.y, dyp); ffma2(Ap, gp.c00_01.x, dxp);
    ull Bp  = mul2(gp.c12_22.x, dzp); ffma2(Bp, gp.c02_11.y, dyp);
    ull Cp  = mul2(gp.c12_22.y, dzp);
    ull ap  = mul2(Cp, dzp); ffma2(ap, Bp, dyp); ffma2(ap, Ap, dxp);
    if (ADD_LI) ap = add2(ap, lip);
    float a0, a1, d20, d21, r20, r21;
    unpk(a0, a1, ap);
    unpk(d20, d21, d2p);
    unpk(r20, r21, gp.nmuz_r2.y);
    float e0, e1;
    asm("ex2.approx.f32 %0, %1;" : "=f"(e0) : "f"(a0));
    asm("ex2.approx.f32 %0, %1;" : "=f"(e1) : "f"(a1));
    w0 = (d20 < r20) ? e0 : 0.f;
    w1 = (d21 < r21) ? e1 : 0.f;
}

// ---------------- prep kernel ----------------
__global__ void prep_kernel(
    const float* __restrict__ mu,
    const float* __restrict__ log_s,
    const float* __restrict__ q,
    const float* __restrict__ F,
    const float* __restrict__ W1,
    const float* __restrict__ b1,
    const float* __restrict__ W2,
    const float* __restrict__ b2)
{
    const int t = threadIdx.x;   // 256 threads, 1 block

    {
        const int k = t;
        float qw = q[k*4+0], qx = q[k*4+1], qy = q[k*4+2], qz = q[k*4+3];
        float inv = 1.0f / (sqrtf(qw*qw + qx*qx + qy*qy + qz*qz) + NEPS);
        qw *= inv; qx *= inv; qy *= inv; qz *= inv;

        float r00 = 1.f - 2.f*(qy*qy + qz*qz);
        float r01 = 2.f*(qx*qy - qw*qz);
        float r02 = 2.f*(qx*qz + qw*qy);
        float r10 = 2.f*(qx*qy + qw*qz);
        float r11 = 1.f - 2.f*(qx*qx + qz*qz);
        float r12 = 2.f*(qy*qz - qw*qx);
        float r20 = 2.f*(qx*qz - qw*qy);
        float r21 = 2.f*(qy*qz + qw*qx);
        float r22 = 1.f - 2.f*(qx*qx + qy*qy);

        float sx = expf(log_s[k*3+0]);
        float sy = expf(log_s[k*3+1]);
        float sz = expf(log_s[k*3+2]);
        float ix = 1.f / (sx*sx + NEPS);
        float iy = 1.f / (sy*sy + NEPS);
        float iz = 1.f / (sz*sz + NEPS);

        float p00 = r00*r00*ix + r01*r01*iy + r02*r02*iz;
        float p01 = r00*r10*ix + r01*r11*iy + r02*r12*iz;
        float p02 = r00*r20*ix + r01*r21*iy + r02*r22*iz;
        float p11 = r10*r10*ix + r11*r11*iy + r12*r12*iz;
        float p12 = r10*r20*ix + r11*r21*iy + r12*r22*iz;
        float p22 = r20*r20*ix + r21*r21*iy + r22*r22*iz;

        float smax = fmaxf(sx, fmaxf(sy, sz));
        float rad = 3.f * smax;

        const float sc = -0.5f * LOG2E;
        float* gpf = reinterpret_cast<float*>(d_prep.gp) + (k >> 1) * 20 + (k & 1);
        gpf[0]  = p00 * sc;
        gpf[2]  = 2.f * p01 * sc;
        gpf[4]  = 2.f * p02 * sc;
        gpf[6]  = p11 * sc;
        gpf[8]  = 2.f * p12 * sc;
        gpf[10] = p22 * sc;
        gpf[12] = -mu[k*3+0];
        gpf[14] = -mu[k*3+1];
        gpf[16] = -mu[k*3+2];
        gpf[18] = rad * rad;
    }
    float* fF = reinterpret_cast<float*>(d_prep.F);
    for (int i = t; i < KG*DG; i += 256) fF[i] = F[i];
    float* fW1 = reinterpret_cast<float*>(d_prep.W1);
    for (int idx = t; idx < HG*16; idx += 256) {
        int j = idx / 16, i = idx % 16;
        fW1[idx] = (i < NIN) ? W1[i*HG + j] : b1[j];
    }
    float* fW2 = reinterpret_cast<float*>(d_prep.W2);
    for (int idx = t; idx < HG*12; idx += 256) {
        int j = idx / 12, c = idx % 12;
        fW2[idx] = (c < CG) ? W2[j*CG + c] : 0.f;
    }
    float* fB2 = reinterpret_cast<float*>(d_prep.b2v);
    if (t < 12) fB2[t] = (t < CG) ? b2[t] : 0.f;
}

// ---------------- main kernel ----------------
__global__ __launch_bounds__(256, 5) void gpc_kernel(
    const float* __restrict__ probe,
    float* __restrict__ out_sh,        // [N,C]
    float* __restrict__ out_latent,    // [N,D]
    float* __restrict__ out_w,         // [N,K]
    int N)
{
    __shared__ float s_st[256 * 36];   // padded staging tile (36 KB)

    const int t    = threadIdx.x;
    const int lane = t & 31;
    const int warp = t >> 5;

    const int nbase  = blockIdx.x * 256;
    const int n      = nbase + t;
    const int nwbase = nbase + warp * 32;
    const bool valid = (n < N);

    float px = 0.f, py = 0.f, pz = 0.f;
    if (valid) { px = probe[n*3+0]; py = probe[n*3+1]; pz = probe[n*3+2]; }

    const ull ppx = bcast2(px);
    const ull ppy = bcast2(py);
    const ull ppz = bcast2(pz);

    float* srow = s_st + t * 36;

    // ---- pass A: sum of gated unnormalized gvals ----
    float sum = 0.f;
    #pragma unroll 8
    for (int p = 0; p < KG/2; p++) {
        float w0, w1;
        eval_pair<false>(c_p.gp[p], ppx, ppy, ppz, 0ull, w0, w1);
        sum += w0;
        sum += w1;
    }
    const float invs = 1.f / (sum + NEPS);
    float li;
    asm("lg2.approx.f32 %0, %1;" : "=f"(li) : "f"(invs));
    const ull lip = bcast2(li);

    // ---- pass B: normalized weights via exp2(arg+li); latent fused ----
    ull l01 = 0ull, l23 = 0ull, l45 = 0ull, l67 = 0ull, l89 = 0ull, lAB = 0ull;

    const int p_off = lane >> 3;   // 0..3  probe within quad
    const int qidx  = lane & 7;    // 0..7  float4 chunk within 32-float segment

    for (int c = 0; c < KG; c += 32) {
        #pragma unroll
        for (int q4 = 0; q4 < 8; q4++) {
            const int k0 = c + q4*4;          // 4 gaussians = 2 pairs
            float w0, w1, w2, w3;
            eval_pair<true>(c_p.gp[(k0 >> 1) + 0], ppx, ppy, ppz, lip, w0, w1);
            eval_pair<true>(c_p.gp[(k0 >> 1) + 1], ppx, ppy, ppz, lip, w2, w3);

            {
                ull ww = bcast2(w0);
                const ulonglong2 fA = c_p.F[(k0+0)*3+0], fB = c_p.F[(k0+0)*3+1], fC = c_p.F[(k0+0)*3+2];
                ffma2(l01, ww, fA.x); ffma2(l23, ww, fA.y);
                ffma2(l45, ww, fB.x); ffma2(l67, ww, fB.y);
                ffma2(l89, ww, fC.x); ffma2(lAB, ww, fC.y);
            }
            {
                ull ww = bcast2(w1);
                const ulonglong2 fA = c_p.F[(k0+1)*3+0], fB = c_p.F[(k0+1)*3+1], fC = c_p.F[(k0+1)*3+2];
                ffma2(l01, ww, fA.x); ffma2(l23, ww, fA.y);
                ffma2(l45, ww, fB.x); ffma2(l67, ww, fB.y);
                ffma2(l89, ww, fC.x); ffma2(lAB, ww, fC.y);
            }
            {
                ull ww = bcast2(w2);
                const ulonglong2 fA = c_p.F[(k0+2)*3+0], fB = c_p.F[(k0+2)*3+1], fC = c_p.F[(k0+2)*3+2];
                ffma2(l01, ww, fA.x); ffma2(l23, ww, fA.y);
                ffma2(l45, ww, fB.x); ffma2(l67, ww, fB.y);
                ffma2(l89, ww, fC.x); ffma2(lAB, ww, fC.y);
            }
            {
                ull ww = bcast2(w3);
                const ulonglong2 fA = c_p.F[(k0+3)*3+0], fB = c_p.F[(k0+3)*3+1], fC = c_p.F[(k0+3)*3+2];
                ffma2(l01, ww, fA.x); ffma2(l23, ww, fA.y);
                ffma2(l45, ww, fB.x); ffma2(l67, ww, fB.y);
                ffma2(l89, ww, fC.x); ffma2(lAB, ww, fC.y);
            }
            *reinterpret_cast<float4*>(srow + q4*4) = make_float4(w0, w1, w2, w3);
        }
        __syncwarp();
        // warp writes 32 probes' 32-float segments; 4 probes per STG.128, full 128B lines
        #pragma unroll
        for (int pb = 0; pb < 32; pb += 4) {
            int p  = pb + p_off;
            int np = nwbase + p;
            if (np < N) {
                float4 v = *reinterpret_cast<const float4*>(&s_st[(warp*32 + p)*36 + qidx*4]);
                *reinterpret_cast<float4*>(&out_w[(size_t)np * KG + c + qidx*4]) = v;
            }
        }
        __syncwarp();
    }

    float lat[DG];
    unpk(lat[0],  lat[1],  l01);
    unpk(lat[2],  lat[3],  l23);
    unpk(lat[4],  lat[5],  l45);
    unpk(lat[6],  lat[7],  l67);
    unpk(lat[8],  lat[9],  l89);
    unpk(lat[10], lat[11], lAB);

    // ---- MLP (weights from constant) ----
    float sh[12];
    {
        float4 B0 = c_p.b2v[0], B1 = c_p.b2v[1], B2 = c_p.b2v[2];
        sh[0] = B0.x; sh[1] = B0.y; sh[2]  = B0.z; sh[3]  = B0.w;
        sh[4] = B1.x; sh[5] = B1.y; sh[6]  = B1.z; sh[7]  = B1.w;
        sh[8] = B2.x; sh[9] = B2.y; sh[10] = B2.z; sh[11] = B2.w;
    }

    #pragma unroll
    for (int j = 0; j < HG; j++) {
        float4 w0 = c_p.W1[j*4+0], w1 = c_p.W1[j*4+1],
               w2 = c_p.W1[j*4+2], w3 = c_p.W1[j*4+3];
        float h = w3.w   // b1[j]
            + lat[0]*w0.x + lat[1]*w0.y + lat[2]*w0.z  + lat[3]*w0.w
            + lat[4]*w1.x + lat[5]*w1.y + lat[6]*w1.z  + lat[7]*w1.w
            + lat[8]*w2.x + lat[9]*w2.y + lat[10]*w2.z + lat[11]*w2.w
            + px*w3.x + py*w3.y + pz*w3.z;
        h = fmaxf(h, 0.f);
        float4 v0 = c_p.W2[j*3+0], v1 = c_p.W2[j*3+1], v2 = c_p.W2[j*3+2];
        sh[0] += h*v0.x; sh[1] += h*v0.y; sh[2]  += h*v0.z; sh[3]  += h*v0.w;
        sh[4] += h*v1.x; sh[5] += h*v1.y; sh[6]  += h*v1.z; sh[7]  += h*v1.w;
        sh[8] += h*v2.x; sh[9] += h*v2.y; sh[10] += h*v2.z; sh[11] += h*v2.w;
    }

    // ---- stage latent (12) + sh (9) -> coalesced output writes ----
    {
        float4* sr4 = reinterpret_cast<float4*>(srow);
        sr4[0] = make_float4(lat[0], lat[1], lat[2],  lat[3]);
        sr4[1] = make_float4(lat[4], lat[5], lat[6],  lat[7]);
        sr4[2] = make_float4(lat[8], lat[9], lat[10], lat[11]);
        srow[12] = sh[0]; srow[13] = sh[1]; srow[14] = sh[2];
        srow[15] = sh[3]; srow[16] = sh[4]; srow[17] = sh[5];
        srow[18] = sh[6]; srow[19] = sh[7]; srow[20] = sh[8];
    }
    __syncwarp();
    #pragma unroll
    for (int i = 0; i < 12; i++) {
        int e = i*32 + lane;
        int p = e / 12, d = e % 12;
        if (nwbase + p < N)
            out_latent[(size_t)nwbase * DG + e] = s_st[(warp*32 + p)*36 + d];
    }
    #pragma unroll
    for (int i = 0; i < 9; i++) {
        int e = i*32 + lane;
        int p = e / 9, d = e % 9;
        if (nwbase + p < N)
            out_sh[(size_t)nwbase * CG + e] = s_st[(warp*32 + p)*36 + 12 + d];
    }
}

extern "C" void kernel_launch(void* const* d_in, const int* in_sizes, int n_in,
                              void* d_out, int out_size) {
    const float* probe = (const float*)d_in[0];
    const float* mu    = (const float*)d_in[1];
    const float* log_s = (const float*)d_in[2];
    const float* q     = (const float*)d_in[3];
    const float* F     = (const float*)d_in[4];
    const float* W1    = (const float*)d_in[5];
    const float* b1    = (const float*)d_in[6];
    const float* W2    = (const float*)d_in[7];
    const float* b2    = (const float*)d_in[8];

    const int N = in_sizes[0] / 3;

    float* out        = (float*)d_out;
    float* out_sh     = out;
    float* out_latent = out + (size_t)N * CG;
    float* out_w      = out_latent + (size_t)N * DG;

    prep_kernel<<<1, 256>>>(mu, log_s, q, F, W1, b1, W2, b2);

    void* prep_ptr = nullptr;
    cudaGetSymbolAddress(&prep_ptr, d_prep);
    cudaMemcpyToSymbolAsync(c_p, prep_ptr, sizeof(CParams), 0,
                            cudaMemcpyDeviceToDevice, 0);

    const int blocks = (N + 255) / 256;
    gpc_kernel<<<blocks, 256>>>(probe, out_sh, out_latent, out_w, N);
}

// round 13
// speedup vs baseline: 1.4264x; 1.4264x over previous
#include <cuda_runtime.h>
#include <cuda_bf16.h>
#include <math.h>

#define KG   256
#define DG   12
#define CG   9
#define HG   32
#define NIN  15
#define NEPS 1e-8f
#define LOG2E 1.4426950408889634f

typedef unsigned long long ull;

struct alignas(16) GPair {                 // params for gaussians (2p, 2p+1)
    ulonglong2 c00_01;   // coeffs pre-scaled by -0.5*log2e (offdiag x2)
    ulonglong2 c02_11;
    ulonglong2 c12_22;
    ulonglong2 nmux_y;   // (-mux pair, -muy pair)
    ulonglong2 nmuz_r2;  // (-muz pair, rad^2 pair)
};

struct CParams {
    GPair       gp[KG/2];     // 10 KB
    ulonglong2  W1[HG * 4];   // 2 KB  (W1^T rows of 16; slot15 = b1[j])
    ulonglong2  W2[HG * 3];   // 1.5 KB (W2 padded to 12)
    ulonglong2  b2v[3];
};

__device__   CParams d_prep;
__constant__ CParams c_p;

// dynamic smem: F table (12KB) + staging tile 256 x 36 floats (36KB)
#define SM_F_FLOATS   (KG * DG)
#define SM_BYTES      ((SM_F_FLOATS + 256*36) * 4)

__device__ __forceinline__ ull add2(ull a, ull b) {
    ull r; asm("add.rn.f32x2 %0, %1, %2;" : "=l"(r) : "l"(a), "l"(b)); return r;
}
__device__ __forceinline__ ull mul2(ull a, ull b) {
    ull r; asm("mul.rn.f32x2 %0, %1, %2;" : "=l"(r) : "l"(a), "l"(b)); return r;
}
__device__ __forceinline__ void ffma2(ull& acc, ull a, ull b) {
    asm("fma.rn.f32x2 %0, %1, %2, %0;" : "+l"(acc) : "l"(a), "l"(b));
}
__device__ __forceinline__ ull bcast2(float x) {
    ull r; asm("mov.b64 %0, {%1, %1};" : "=l"(r) : "f"(x)); return r;
}
__device__ __forceinline__ ull pack2(float lo, float hi) {
    ull r; asm("mov.b64 %0, {%1, %2};" : "=l"(r) : "f"(lo), "f"(hi)); return r;
}
__device__ __forceinline__ void unpk(float& lo, float& hi, ull p) {
    asm("mov.b64 {%0, %1}, %2;" : "=f"(lo), "=f"(hi) : "l"(p));
}

template<bool ADD_LI>
__device__ __forceinline__ void eval_pair(
    const GPair& gp, ull ppx, ull ppy, ull ppz, ull lip,
    float& w0, float& w1)
{
    ull dxp = add2(ppx, gp.nmux_y.x);
    ull dyp = add2(ppy, gp.nmux_y.y);
    ull dzp = add2(ppz, gp.nmuz_r2.x);
    ull d2p = mul2(dzp, dzp); ffma2(d2p, dyp, dyp); ffma2(d2p, dxp, dxp);
    ull Ap  = mul2(gp.c02_11.x, dzp); ffma2(Ap, gp.c00_01.y, dyp); ffma2(Ap, gp.c00_01.x, dxp);
    ull Bp  = mul2(gp.c12_22.x, dzp); ffma2(Bp, gp.c02_11.y, dyp);
    ull Cp  = mul2(gp.c12_22.y, dzp);
    ull ap  = mul2(Cp, dzp); ffma2(ap, Bp, dyp); ffma2(ap, Ap, dxp);
    if (ADD_LI) ap = add2(ap, lip);
    float a0, a1, d20, d21, r20, r21;
    unpk(a0, a1, ap);
    unpk(d20, d21, d2p);
    unpk(r20, r21, gp.nmuz_r2.y);
    float e0, e1;
    asm("ex2.approx.f32 %0, %1;" : "=f"(e0) : "f"(a0));
    asm("ex2.approx.f32 %0, %1;" : "=f"(e1) : "f"(a1));
    w0 = (d20 < r20) ? e0 : 0.f;
    w1 = (d21 < r21) ? e1 : 0.f;
}

// ---------------- prep kernel ----------------
__global__ void prep_kernel(
    const float* __restrict__ mu,
    const float* __restrict__ log_s,
    const float* __restrict__ q,
    const float* __restrict__ W1,
    const float* __restrict__ b1,
    const float* __restrict__ W2,
    const float* __restrict__ b2)
{
    const int t = threadIdx.x;   // 256 threads, 1 block

    {
        const int k = t;
        float qw = q[k*4+0], qx = q[k*4+1], qy = q[k*4+2], qz = q[k*4+3];
        float inv = 1.0f / (sqrtf(qw*qw + qx*qx + qy*qy + qz*qz) + NEPS);
        qw *= inv; qx *= inv; qy *= inv; qz *= inv;

        float r00 = 1.f - 2.f*(qy*qy + qz*qz);
        float r01 = 2.f*(qx*qy - qw*qz);
        float r02 = 2.f*(qx*qz + qw*qy);
        float r10 = 2.f*(qx*qy + qw*qz);
        float r11 = 1.f - 2.f*(qx*qx + qz*qz);
        float r12 = 2.f*(qy*qz - qw*qx);
        float r20 = 2.f*(qx*qz - qw*qy);
        float r21 = 2.f*(qy*qz + qw*qx);
        float r22 = 1.f - 2.f*(qx*qx + qy*qy);

        float sx = expf(log_s[k*3+0]);
        float sy = expf(log_s[k*3+1]);
        float sz = expf(log_s[k*3+2]);
        float ix = 1.f / (sx*sx + NEPS);
        float iy = 1.f / (sy*sy + NEPS);
        float iz = 1.f / (sz*sz + NEPS);

        float p00 = r00*r00*ix + r01*r01*iy + r02*r02*iz;
        float p01 = r00*r10*ix + r01*r11*iy + r02*r12*iz;
        float p02 = r00*r20*ix + r01*r21*iy + r02*r22*iz;
        float p11 = r10*r10*ix + r11*r11*iy + r12*r12*iz;
        float p12 = r10*r20*ix + r11*r21*iy + r12*r22*iz;
        float p22 = r20*r20*ix + r21*r21*iy + r22*r22*iz;

        float smax = fmaxf(sx, fmaxf(sy, sz));
        float rad = 3.f * smax;

        const float sc = -0.5f * LOG2E;
        float* gpf = reinterpret_cast<float*>(d_prep.gp) + (k >> 1) * 20 + (k & 1);
        gpf[0]  = p00 * sc;
        gpf[2]  = 2.f * p01 * sc;
        gpf[4]  = 2.f * p02 * sc;
        gpf[6]  = p11 * sc;
        gpf[8]  = 2.f * p12 * sc;
        gpf[10] = p22 * sc;
        gpf[12] = -mu[k*3+0];
        gpf[14] = -mu[k*3+1];
        gpf[16] = -mu[k*3+2];
        gpf[18] = rad * rad;
    }
    float* fW1 = reinterpret_cast<float*>(d_prep.W1);
    for (int idx = t; idx < HG*16; idx += 256) {
        int j = idx / 16, i = idx % 16;
        fW1[idx] = (i < NIN) ? W1[i*HG + j] : b1[j];
    }
    float* fW2 = reinterpret_cast<float*>(d_prep.W2);
    for (int idx = t; idx < HG*12; idx += 256) {
        int j = idx / 12, c = idx % 12;
        fW2[idx] = (c < CG) ? W2[j*CG + c] : 0.f;
    }
    float* fB2 = reinterpret_cast<float*>(d_prep.b2v);
    if (t < 12) fB2[t] = (t < CG) ? b2[t] : 0.f;
}

// ---------------- main kernel ----------------
__global__ __launch_bounds__(256, 4) void gpc_kernel(
    const float* __restrict__ probe,
    const float* __restrict__ Fg,      // [K,D] global
    float* __restrict__ out_sh,        // [N,C]
    float* __restrict__ out_latent,    // [N,D]
    float* __restrict__ out_w,         // [N,K]
    int N)
{
    extern __shared__ float sm[];
    float* s_F  = sm;                       // 3072 floats
    float* s_st = sm + SM_F_FLOATS;         // 256 x 36 floats

    const int t    = threadIdx.x;
    const int lane = t & 31;
    const int warp = t >> 5;

    // load F to shared (coalesced float4)
    {
        const float4* src = reinterpret_cast<const float4*>(Fg);
        float4* dst = reinterpret_cast<float4*>(s_F);
        #pragma unroll
        for (int i = t; i < SM_F_FLOATS/4; i += 256) dst[i] = src[i];
    }
    __syncthreads();

    const int nbase  = blockIdx.x * 256;
    const int n      = nbase + t;
    const int nwbase = nbase + warp * 32;
    const bool valid = (n < N);

    float px = 0.f, py = 0.f, pz = 0.f;
    if (valid) { px = probe[n*3+0]; py = probe[n*3+1]; pz = probe[n*3+2]; }

    const ull ppx = bcast2(px);
    const ull ppy = bcast2(py);
    const ull ppz = bcast2(pz);

    float* srow = s_st + t * 36;

    // ---- pass A: sum of gated unnormalized gvals (GPair from constant) ----
    float sum = 0.f;
    #pragma unroll 8
    for (int p = 0; p < KG/2; p++) {
        float w0, w1;
        eval_pair<false>(c_p.gp[p], ppx, ppy, ppz, 0ull, w0, w1);
        sum += w0;
        sum += w1;
    }
    const float invs = 1.f / (sum + NEPS);
    float li;
    asm("lg2.approx.f32 %0, %1;" : "=f"(li) : "f"(invs));
    const ull lip = bcast2(li);

    // ---- pass B: normalized weights via exp2(arg+li); latent fused (F shared) ----
    ull l01 = 0ull, l23 = 0ull, l45 = 0ull, l67 = 0ull, l89 = 0ull, lAB = 0ull;

    const int p_off = lane >> 3;   // 0..3
    const int qidx  = lane & 7;    // 0..7

    const ulonglong2* sF = reinterpret_cast<const ulonglong2*>(s_F);

    for (int c = 0; c < KG; c += 32) {
        #pragma unroll
        for (int q4 = 0; q4 < 8; q4++) {
            const int k0 = c + q4*4;          // 4 gaussians = 2 pairs
            float w0, w1, w2, w3;
            eval_pair<true>(c_p.gp[(k0 >> 1) + 0], ppx, ppy, ppz, lip, w0, w1);
            eval_pair<true>(c_p.gp[(k0 >> 1) + 1], ppx, ppy, ppz, lip, w2, w3);

            {
                ull ww = bcast2(w0);
                const ulonglong2 fA = sF[(k0+0)*3+0], fB = sF[(k0+0)*3+1], fC = sF[(k0+0)*3+2];
                ffma2(l01, ww, fA.x); ffma2(l23, ww, fA.y);
                ffma2(l45, ww, fB.x); ffma2(l67, ww, fB.y);
                ffma2(l89, ww, fC.x); ffma2(lAB, ww, fC.y);
            }
            {
                ull ww = bcast2(w1);
                const ulonglong2 fA = sF[(k0+1)*3+0], fB = sF[(k0+1)*3+1], fC = sF[(k0+1)*3+2];
                ffma2(l01, ww, fA.x); ffma2(l23, ww, fA.y);
                ffma2(l45, ww, fB.x); ffma2(l67, ww, fB.y);
                ffma2(l89, ww, fC.x); ffma2(lAB, ww, fC.y);
            }
            {
                ull ww = bcast2(w2);
                const ulonglong2 fA = sF[(k0+2)*3+0], fB = sF[(k0+2)*3+1], fC = sF[(k0+2)*3+2];
                ffma2(l01, ww, fA.x); ffma2(l23, ww, fA.y);
                ffma2(l45, ww, fB.x); ffma2(l67, ww, fB.y);
                ffma2(l89, ww, fC.x); ffma2(lAB, ww, fC.y);
            }
            {
                ull ww = bcast2(w3);
                const ulonglong2 fA = sF[(k0+3)*3+0], fB = sF[(k0+3)*3+1], fC = sF[(k0+3)*3+2];
                ffma2(l01, ww, fA.x); ffma2(l23, ww, fA.y);
                ffma2(l45, ww, fB.x); ffma2(l67, ww, fB.y);
                ffma2(l89, ww, fC.x); ffma2(lAB, ww, fC.y);
            }
            *reinterpret_cast<float4*>(srow + q4*4) = make_float4(w0, w1, w2, w3);
        }
        __syncwarp();
        // warp writes 32 probes' 32-float segments; 4 probes per STG.128 (full lines)
        #pragma unroll
        for (int pb = 0; pb < 32; pb += 4) {
            int p  = pb + p_off;
            int np = nwbase + p;
            if (np < N) {
                float4 v = *reinterpret_cast<const float4*>(&s_st[(warp*32 + p)*36 + qidx*4]);
                *reinterpret_cast<float4*>(&out_w[(size_t)np * KG + c + qidx*4]) = v;
            }
        }
        __syncwarp();
    }

    // ---- MLP entirely in f32x2 packs (latent packs are already normalized) ----
    const ull pxy = pack2(px, py);
    const ull pz1 = pack2(pz, 1.0f);

    ull s0 = c_p.b2v[0].x, s1 = c_p.b2v[0].y, s2 = c_p.b2v[1].x,
        s3 = c_p.b2v[1].y, s4 = c_p.b2v[2].x, s5 = c_p.b2v[2].y;

    #pragma unroll
    for (int j = 0; j < HG; j++) {
        const ulonglong2 u0 = c_p.W1[j*4+0], u1 = c_p.W1[j*4+1],
                         u2 = c_p.W1[j*4+2], u3 = c_p.W1[j*4+3];
        ull hp = mul2(l01, u0.x);
        ffma2(hp, l23, u0.y);
        ffma2(hp, l45, u1.x);
        ffma2(hp, l67, u1.y);
        ffma2(hp, l89, u2.x);
        ffma2(hp, lAB, u2.y);
        ffma2(hp, pxy, u3.x);
        ffma2(hp, pz1, u3.y);     // includes pz*w14 + 1.0*b1[j]
        float hlo, hhi;
        unpk(hlo, hhi, hp);
        float h = fmaxf(hlo + hhi, 0.f);
        ull hh = bcast2(h);
        const ulonglong2 v0 = c_p.W2[j*3+0], v1 = c_p.W2[j*3+1], v2 = c_p.W2[j*3+2];
        ffma2(s0, hh, v0.x); ffma2(s1, hh, v0.y);
        ffma2(s2, hh, v1.x); ffma2(s3, hh, v1.y);
        ffma2(s4, hh, v2.x); ffma2(s5, hh, v2.y);
    }

    float lat[DG];
    unpk(lat[0],  lat[1],  l01);
    unpk(lat[2],  lat[3],  l23);
    unpk(lat[4],  lat[5],  l45);
    unpk(lat[6],  lat[7],  l67);
    unpk(lat[8],  lat[9],  l89);
    unpk(lat[10], lat[11], lAB);

    float sh[12];
    unpk(sh[0],  sh[1],  s0);
    unpk(sh[2],  sh[3],  s1);
    unpk(sh[4],  sh[5],  s2);
    unpk(sh[6],  sh[7],  s3);
    unpk(sh[8],  sh[9],  s4);
    unpk(sh[10], sh[11], s5);

    // ---- stage latent (12) + sh (9) -> coalesced output writes ----
    {
        float4* sr4 = reinterpret_cast<float4*>(srow);
        sr4[0] = make_float4(lat[0], lat[1], lat[2],  lat[3]);
        sr4[1] = make_float4(lat[4], lat[5], lat[6],  lat[7]);
        sr4[2] = make_float4(lat[8], lat[9], lat[10], lat[11]);
        srow[12] = sh[0]; srow[13] = sh[1]; srow[14] = sh[2];
        srow[15] = sh[3]; srow[16] = sh[4]; srow[17] = sh[5];
        srow[18] = sh[6]; srow[19] = sh[7]; srow[20] = sh[8];
    }
    __syncwarp();
    #pragma unroll
    for (int i = 0; i < 12; i++) {
        int e = i*32 + lane;
        int p = e / 12, d = e % 12;
        if (nwbase + p < N)
            out_latent[(size_t)nwbase * DG + e] = s_st[(warp*32 + p)*36 + d];
    }
    #pragma unroll
    for (int i = 0; i < 9; i++) {
        int e = i*32 + lane;
        int p = e / 9, d = e % 9;
        if (nwbase + p < N)
            out_sh[(size_t)nwbase * CG + e] = s_st[(warp*32 + p)*36 + 12 + d];
    }
}

extern "C" void kernel_launch(void* const* d_in, const int* in_sizes, int n_in,
                              void* d_out, int out_size) {
    const float* probe = (const float*)d_in[0];
    const float* mu    = (const float*)d_in[1];
    const float* log_s = (const float*)d_in[2];
    const float* q     = (const float*)d_in[3];
    const float* F     = (const float*)d_in[4];
    const float* W1    = (const float*)d_in[5];
    const float* b1    = (const float*)d_in[6];
    const float* W2    = (const float*)d_in[7];
    const float* b2    = (const float*)d_in[8];

    const int N = in_sizes[0] / 3;

    float* out        = (float*)d_out;
    float* out_sh     = out;
    float* out_latent = out + (size_t)N * CG;
    float* out_w      = out_latent + (size_t)N * DG;

    prep_kernel<<<1, 256>>>(mu, log_s, q, W1, b1, W2, b2);

    void* prep_ptr = nullptr;
    cudaGetSymbolAddress(&prep_ptr, d_prep);
    cudaMemcpyToSymbolAsync(c_p, prep_ptr, sizeof(CParams), 0,
                            cudaMemcpyDeviceToDevice, 0);

    cudaFuncSetAttribute(gpc_kernel, cudaFuncAttributeMaxDynamicSharedMemorySize,
                         SM_BYTES);

    const int blocks = (N + 255) / 256;
    gpc_kernel<<<blocks, 256, SM_BYTES>>>(probe, F, out_sh, out_latent, out_w, N);
}